// round 12
// baseline (speedup 1.0000x reference)
#include <cuda_runtime.h>
#include <cstdint>

#define N_TOKENS 8192
#define IN_CH    4096
#define OUT_CH   4096
#define RANK     16
#define TOK      16                    // tokens per block
#define KH       1024                  // k chunk staged (R: 16 x 1024 = 64 KB)
#define NKCH     (IN_CH / KH)          // 4
#define OCH      1024                  // o chunk per B-iteration
#define NOCH     (OUT_CH / OCH)        // 4
#define DSMEM    (RANK * KH * 4)       // 64 KB

typedef unsigned long long u64;

__device__ __forceinline__ u64 f2fma(u64 a, u64 b, u64 c) {
    u64 d;
    asm("fma.rn.f32x2 %0, %1, %2, %3;" : "=l"(d) : "l"(a), "l"(b), "l"(c));
    return d;
}
__device__ __forceinline__ u64 splat2(float v) {
    u64 d;
    asm("mov.b64 %0, {%1, %1};" : "=l"(d) : "f"(v));
    return d;
}
__device__ __forceinline__ u64 pack2(float lo, float hi) {
    u64 d;
    asm("mov.b64 %0, {%1, %2};" : "=l"(d) : "f"(lo), "f"(hi));
    return d;
}

// ----------------------------------------------------------------------------
// Fused low-rank linear: out = x @ (L@R)^T + bias, ONE kernel, occupancy 2.
// Block: 16 tokens, 256 thr (8 warps), 64 KB dynamic smem (R chunk), 2 KB ts2.
// Phase A: 4 chunks { stage R[16][1024] -> smem; warp = 4 tok x 8 ranks }.
// Phase B: 4 o-chunks { L rows -> 64 packed regs straight from L2 (no smem,
//          no barriers); 2 passes of 8 tokens; t2 broadcast LDS.64 1:2 }.
// ----------------------------------------------------------------------------
__global__ void __launch_bounds__(256, 2)
fused(const float* __restrict__ x, const float* __restrict__ Rm,
      const float* __restrict__ Lm, const float* __restrict__ bias,
      float* __restrict__ out) {
    extern __shared__ __align__(16) float Rs[];        // [RANK][KH] 64 KB
    __shared__ __align__(16) u64 ts2[TOK][RANK];       // 2 KB

    const int tid  = threadIdx.x;
    const int warp = tid >> 5;
    const int lane = tid & 31;
    const int tokbase = blockIdx.x * TOK;

    // ---------------- Phase A: t = x @ R^T ----------------
    const int q     = warp >> 1;          // token quad 0..3
    const int rh    = warp & 1;           // rank half
    const int tok0  = q * 4;
    const int rbase = rh * 8;

    u64 acc[4][8];
#pragma unroll
    for (int t = 0; t < 4; t++)
#pragma unroll
        for (int r = 0; r < 8; r++) acc[t][r] = 0ull;

    const float* xg = x + (size_t)(tokbase + tok0) * IN_CH;

#pragma unroll 1
    for (int c = 0; c < NKCH; c++) {
        if (c > 0) __syncthreads();               // done reading previous chunk
        // stage R[0:16][c*KH..]: 4096 float4, 16 per thread, coalesced
#pragma unroll
        for (int j = 0; j < 16; j++) {
            const int linear = tid + 256 * j;
            const int row    = linear >> 8;        // KH/4 = 256 float4 per row
            const int colf   = (linear & 255) << 2;
            *reinterpret_cast<float4*>(&Rs[row * KH + colf]) =
                *reinterpret_cast<const float4*>(&Rm[(size_t)row * IN_CH + c * KH + colf]);
        }
        __syncthreads();

        const float* xh = xg + c * KH + lane * 4;
        const float* Rw = Rs + (size_t)rbase * KH + lane * 4;
#pragma unroll 2
        for (int i = 0; i < KH / 128; i++) {       // 8 iters
            const int kk = i * 128;
            const uint4 xv0 = __ldcs(reinterpret_cast<const uint4*>(xh + 0 * IN_CH + kk));
            const uint4 xv1 = __ldcs(reinterpret_cast<const uint4*>(xh + 1 * IN_CH + kk));
            const uint4 xv2 = __ldcs(reinterpret_cast<const uint4*>(xh + 2 * IN_CH + kk));
            const uint4 xv3 = __ldcs(reinterpret_cast<const uint4*>(xh + 3 * IN_CH + kk));
            const ulonglong2 x0 = *reinterpret_cast<const ulonglong2*>(&xv0);
            const ulonglong2 x1 = *reinterpret_cast<const ulonglong2*>(&xv1);
            const ulonglong2 x2 = *reinterpret_cast<const ulonglong2*>(&xv2);
            const ulonglong2 x3 = *reinterpret_cast<const ulonglong2*>(&xv3);
#pragma unroll
            for (int r = 0; r < 8; r++) {
                const ulonglong2 rv =
                    *reinterpret_cast<const ulonglong2*>(Rw + (size_t)r * KH + kk);
                acc[0][r] = f2fma(x0.x, rv.x, acc[0][r]);
                acc[0][r] = f2fma(x0.y, rv.y, acc[0][r]);
                acc[1][r] = f2fma(x1.x, rv.x, acc[1][r]);
                acc[1][r] = f2fma(x1.y, rv.y, acc[1][r]);
                acc[2][r] = f2fma(x2.x, rv.x, acc[2][r]);
                acc[2][r] = f2fma(x2.y, rv.y, acc[2][r]);
                acc[3][r] = f2fma(x3.x, rv.x, acc[3][r]);
                acc[3][r] = f2fma(x3.y, rv.y, acc[3][r]);
            }
        }
    }

    // lane-reduce; lane 0 splats this warp's (4 tok x 8 ranks) into ts2
#pragma unroll
    for (int t = 0; t < 4; t++) {
        float sv[8];
#pragma unroll
        for (int r = 0; r < 8; r++) {
            float2 v = *reinterpret_cast<float2*>(&acc[t][r]);
            sv[r] = v.x + v.y;
        }
#pragma unroll
        for (int off = 16; off > 0; off >>= 1) {
#pragma unroll
            for (int r = 0; r < 8; r++)
                sv[r] += __shfl_xor_sync(0xffffffffu, sv[r], off);
        }
        if (lane == 0) {
#pragma unroll
            for (int r = 0; r < 8; r++)
                ts2[tok0 + t][rbase + r] = splat2(sv[r]);
        }
    }
    __syncthreads();   // ts2 complete

    // ---------------- Phase B: out = t @ L^T + bias ----------------
#pragma unroll 1
    for (int c = 0; c < NOCH; c++) {
        const int og = c * OCH + tid * 4;          // 4 consecutive outputs

        // L[og..og+3][0..15] -> packed regs: Lp0[r]=(L[og],L[og+1]),
        // Lp1[r]=(L[og+2],L[og+3]). 16 coalesced float4 loads (L2-resident).
        u64 Lp0[16], Lp1[16];
        {
            float4 v[4][4];
#pragma unroll
            for (int i = 0; i < 4; i++) {
                const float4* lr = reinterpret_cast<const float4*>(
                    Lm + (size_t)(og + i) * RANK);
                v[i][0] = lr[0]; v[i][1] = lr[1]; v[i][2] = lr[2]; v[i][3] = lr[3];
            }
#pragma unroll
            for (int qq = 0; qq < 4; qq++) {
                Lp0[qq * 4 + 0] = pack2(v[0][qq].x, v[1][qq].x);
                Lp0[qq * 4 + 1] = pack2(v[0][qq].y, v[1][qq].y);
                Lp0[qq * 4 + 2] = pack2(v[0][qq].z, v[1][qq].z);
                Lp0[qq * 4 + 3] = pack2(v[0][qq].w, v[1][qq].w);
                Lp1[qq * 4 + 0] = pack2(v[2][qq].x, v[3][qq].x);
                Lp1[qq * 4 + 1] = pack2(v[2][qq].y, v[3][qq].y);
                Lp1[qq * 4 + 2] = pack2(v[2][qq].z, v[3][qq].z);
                Lp1[qq * 4 + 3] = pack2(v[2][qq].w, v[3][qq].w);
            }
        }
        const ulonglong2 bv = *reinterpret_cast<const ulonglong2*>(&bias[og]);

        // two passes of 8 tokens (keeps oacc at 32 regs)
#pragma unroll
        for (int tp = 0; tp < 2; tp++) {
            u64 accA[8], accB[8];
#pragma unroll
            for (int tk = 0; tk < 8; tk++) { accA[tk] = bv.x; accB[tk] = bv.y; }

#pragma unroll
            for (int r = 0; r < RANK; r++) {
#pragma unroll
                for (int tk = 0; tk < 8; tk++) {
                    const u64 t2 = ts2[tp * 8 + tk][r];   // broadcast LDS.64
                    accA[tk] = f2fma(t2, Lp0[r], accA[tk]);
                    accB[tk] = f2fma(t2, Lp1[r], accB[tk]);
                }
            }

#pragma unroll
            for (int tk = 0; tk < 8; tk++) {
                ulonglong2 o;
                o.x = accA[tk];
                o.y = accB[tk];
                *reinterpret_cast<ulonglong2*>(
                    out + (size_t)(tokbase + tp * 8 + tk) * OUT_CH + og) = o;
            }
        }
    }
}

extern "C" void kernel_launch(void* const* d_in, const int* in_sizes, int n_in,
                              void* d_out, int out_size) {
    (void)in_sizes; (void)n_in; (void)out_size;
    const float* x    = (const float*)d_in[0];   // [8192, 4096]
    const float* Lm   = (const float*)d_in[1];   // [4096, 16]
    const float* Rm   = (const float*)d_in[2];   // [16, 4096]
    const float* bias = (const float*)d_in[3];   // [4096]
    float* out = (float*)d_out;                  // [8192, 4096]

    cudaFuncSetAttribute(fused, cudaFuncAttributeMaxDynamicSharedMemorySize, DSMEM);
    fused<<<N_TOKENS / TOK, 256, DSMEM>>>(x, Rm, Lm, bias, out);
}

// round 14
// speedup vs baseline: 2.9289x; 2.9289x over previous
#include <cuda_runtime.h>
#include <cstdint>

#define N_TOKENS 8192
#define IN_CH    4096
#define OUT_CH   4096
#define RANK     16
#define TOK      16                    // tokens per block
#define KH       1024                  // k chunk staged (R: 16 x 1024 = 64 KB)
#define NKCH     (IN_CH / KH)          // 4
#define OCH      1024                  // o chunk staged (Lt: 16 x 1024 = 64 KB)
#define NOCH     (OUT_CH / OCH)        // 4
#define DSMEM    (RANK * KH * 4)       // 64 KB

typedef unsigned long long u64;

__device__ __forceinline__ u64 f2fma(u64 a, u64 b, u64 c) {
    u64 d;
    asm("fma.rn.f32x2 %0, %1, %2, %3;" : "=l"(d) : "l"(a), "l"(b), "l"(c));
    return d;
}
__device__ __forceinline__ u64 splat2(float v) {
    u64 d;
    asm("mov.b64 %0, {%1, %1};" : "=l"(d) : "f"(v));
    return d;
}

// ----------------------------------------------------------------------------
// Fused low-rank linear: out = x @ (L@R)^T + bias. ONE kernel, occupancy 2,
// NO register spills (phase B reads L from smem; max live regs ~90).
// Block: 16 tokens, 256 thr (8 warps), 64 KB dynamic smem reused Rs -> Lt.
// Phase A: 4 chunks { stage R[16][1024]; warp = 4 tok x 8 ranks }.
// Phase B: 4 chunks { stage Lt[16][1024] transposed; thread = 4 outputs x
//          16 tokens, oacc 64 regs; per r: 1 LDS.128 + 16 bcast LDS.64 }.
// ----------------------------------------------------------------------------
__global__ void __launch_bounds__(256, 2)
fused(const float* __restrict__ x, const float* __restrict__ Rm,
      const float* __restrict__ Lm, const float* __restrict__ bias,
      float* __restrict__ out) {
    extern __shared__ __align__(16) float sbuf[];      // 64 KB: Rs then Lt
    __shared__ __align__(16) u64 ts2[TOK][RANK];       // 2 KB

    const int tid  = threadIdx.x;
    const int warp = tid >> 5;
    const int lane = tid & 31;
    const int tokbase = blockIdx.x * TOK;

    // ---------------- Phase A: t = x @ R^T ----------------
    const int q     = warp >> 1;          // token quad 0..3
    const int rh    = warp & 1;           // rank half
    const int tok0  = q * 4;
    const int rbase = rh * 8;

    u64 acc[4][8];
#pragma unroll
    for (int t = 0; t < 4; t++)
#pragma unroll
        for (int r = 0; r < 8; r++) acc[t][r] = 0ull;

    const float* xg = x + (size_t)(tokbase + tok0) * IN_CH;

#pragma unroll 1
    for (int c = 0; c < NKCH; c++) {
        if (c > 0) __syncthreads();               // done reading previous chunk
        // stage R[0:16][c*KH..]: 4096 float4, 16 per thread, coalesced
#pragma unroll
        for (int j = 0; j < 16; j++) {
            const int linear = tid + 256 * j;
            const int row    = linear >> 8;        // KH/4 = 256 float4 per row
            const int colf   = (linear & 255) << 2;
            *reinterpret_cast<float4*>(&sbuf[row * KH + colf]) =
                *reinterpret_cast<const float4*>(&Rm[(size_t)row * IN_CH + c * KH + colf]);
        }
        __syncthreads();

        const float* xh = xg + c * KH + lane * 4;
        const float* Rw = sbuf + (size_t)rbase * KH + lane * 4;
#pragma unroll 2
        for (int i = 0; i < KH / 128; i++) {       // 8 iters
            const int kk = i * 128;
            const uint4 xv0 = __ldcs(reinterpret_cast<const uint4*>(xh + 0 * IN_CH + kk));
            const uint4 xv1 = __ldcs(reinterpret_cast<const uint4*>(xh + 1 * IN_CH + kk));
            const uint4 xv2 = __ldcs(reinterpret_cast<const uint4*>(xh + 2 * IN_CH + kk));
            const uint4 xv3 = __ldcs(reinterpret_cast<const uint4*>(xh + 3 * IN_CH + kk));
            const ulonglong2 x0 = *reinterpret_cast<const ulonglong2*>(&xv0);
            const ulonglong2 x1 = *reinterpret_cast<const ulonglong2*>(&xv1);
            const ulonglong2 x2 = *reinterpret_cast<const ulonglong2*>(&xv2);
            const ulonglong2 x3 = *reinterpret_cast<const ulonglong2*>(&xv3);
#pragma unroll
            for (int r = 0; r < 8; r++) {
                const ulonglong2 rv =
                    *reinterpret_cast<const ulonglong2*>(Rw + (size_t)r * KH + kk);
                acc[0][r] = f2fma(x0.x, rv.x, acc[0][r]);
                acc[0][r] = f2fma(x0.y, rv.y, acc[0][r]);
                acc[1][r] = f2fma(x1.x, rv.x, acc[1][r]);
                acc[1][r] = f2fma(x1.y, rv.y, acc[1][r]);
                acc[2][r] = f2fma(x2.x, rv.x, acc[2][r]);
                acc[2][r] = f2fma(x2.y, rv.y, acc[2][r]);
                acc[3][r] = f2fma(x3.x, rv.x, acc[3][r]);
                acc[3][r] = f2fma(x3.y, rv.y, acc[3][r]);
            }
        }
    }

    // lane-reduce; lane 0 splats this warp's (4 tok x 8 ranks) into ts2
#pragma unroll
    for (int t = 0; t < 4; t++) {
        float sv[8];
#pragma unroll
        for (int r = 0; r < 8; r++) {
            float2 v = *reinterpret_cast<float2*>(&acc[t][r]);
            sv[r] = v.x + v.y;
        }
#pragma unroll
        for (int off = 16; off > 0; off >>= 1) {
#pragma unroll
            for (int r = 0; r < 8; r++)
                sv[r] += __shfl_xor_sync(0xffffffffu, sv[r], off);
        }
        if (lane == 0) {
#pragma unroll
            for (int r = 0; r < 8; r++)
                ts2[tok0 + t][rbase + r] = splat2(sv[r]);
        }
    }

    // ---------------- Phase B: out = t @ L^T + bias ----------------
#pragma unroll 1
    for (int c = 0; c < NOCH; c++) {
        __syncthreads();   // done reading Rs (c==0: also covers ts2 writes) / prev Lt
        // stage Lt[r][ol]: 1024 rows x 16 floats, 4 rows per thread
#pragma unroll
        for (int j = 0; j < 4; j++) {
            const int ol = tid + 256 * j;
            const float4* lr = reinterpret_cast<const float4*>(
                Lm + (size_t)(c * OCH + ol) * RANK);
            float4 a = lr[0], b = lr[1], d2 = lr[2], e = lr[3];
            sbuf[0 * OCH + ol]  = a.x;  sbuf[1 * OCH + ol]  = a.y;
            sbuf[2 * OCH + ol]  = a.z;  sbuf[3 * OCH + ol]  = a.w;
            sbuf[4 * OCH + ol]  = b.x;  sbuf[5 * OCH + ol]  = b.y;
            sbuf[6 * OCH + ol]  = b.z;  sbuf[7 * OCH + ol]  = b.w;
            sbuf[8 * OCH + ol]  = d2.x; sbuf[9 * OCH + ol]  = d2.y;
            sbuf[10 * OCH + ol] = d2.z; sbuf[11 * OCH + ol] = d2.w;
            sbuf[12 * OCH + ol] = e.x;  sbuf[13 * OCH + ol] = e.y;
            sbuf[14 * OCH + ol] = e.z;  sbuf[15 * OCH + ol] = e.w;
        }
        __syncthreads();

        const int ol4 = tid * 4;
        const int og  = c * OCH + ol4;
        const ulonglong2 bv = *reinterpret_cast<const ulonglong2*>(&bias[og]);

        u64 oacc[TOK][2];
#pragma unroll
        for (int t = 0; t < TOK; t++) { oacc[t][0] = bv.x; oacc[t][1] = bv.y; }

#pragma unroll
        for (int r = 0; r < RANK; r++) {
            const ulonglong2 Lv =
                *reinterpret_cast<const ulonglong2*>(&sbuf[r * OCH + ol4]);
#pragma unroll
            for (int t = 0; t < TOK; t++) {
                const u64 t2 = ts2[t][r];          // broadcast LDS.64
                oacc[t][0] = f2fma(t2, Lv.x, oacc[t][0]);
                oacc[t][1] = f2fma(t2, Lv.y, oacc[t][1]);
            }
        }

        float* op = out + (size_t)tokbase * OUT_CH + og;
#pragma unroll
        for (int t = 0; t < TOK; t++) {
            ulonglong2 o;
            o.x = oacc[t][0];
            o.y = oacc[t][1];
            *reinterpret_cast<ulonglong2*>(op + (size_t)t * OUT_CH) = o;
        }
    }
}

extern "C" void kernel_launch(void* const* d_in, const int* in_sizes, int n_in,
                              void* d_out, int out_size) {
    (void)in_sizes; (void)n_in; (void)out_size;
    const float* x    = (const float*)d_in[0];   // [8192, 4096]
    const float* Lm   = (const float*)d_in[1];   // [4096, 16]
    const float* Rm   = (const float*)d_in[2];   // [16, 4096]
    const float* bias = (const float*)d_in[3];   // [4096]
    float* out = (float*)d_out;                  // [8192, 4096]

    cudaFuncSetAttribute(fused, cudaFuncAttributeMaxDynamicSharedMemorySize, DSMEM);
    fused<<<N_TOKENS / TOK, 256, DSMEM>>>(x, Rm, Lm, bias, out);
}

// round 16
// speedup vs baseline: 3.5169x; 1.2008x over previous
#include <cuda_runtime.h>
#include <cstdint>

#define N_TOKENS 8192
#define IN_CH    4096
#define OUT_CH   4096
#define RANK     16
#define KSLICES  2
#define KS       (IN_CH / KSLICES)    // 2048 k per slice
#define K1_SMEM  (RANK * KS * 4)      // 128 KB

typedef unsigned long long u64;

// partial t sums per k-slice: g_tp[slice][token][rank]
__device__ float g_tp[KSLICES][N_TOKENS][RANK];

__device__ __forceinline__ u64 f2fma(u64 a, u64 b, u64 c) {
    u64 d;
    asm("fma.rn.f32x2 %0, %1, %2, %3;" : "=l"(d) : "l"(a), "l"(b), "l"(c));
    return d;
}
__device__ __forceinline__ u64 splat2(float v) {
    u64 d;
    asm("mov.b64 %0, {%1, %1};" : "=l"(d) : "f"(v));
    return d;
}

// ----------------------------------------------------------------------------
// Kernel 1 (round-10 exact, measured ~53 us):
// g_tp[ks][n][r] = sum_{k in slice} x[n,k] * R[r,k]
// KSLICES=2: 128 KB R-slice staged once per block; 512 thr = 16 warps;
// warp = 4 tok x 8 ranks.
// ----------------------------------------------------------------------------
__global__ void __launch_bounds__(512)
k1_xRt(const float* __restrict__ x, const float* __restrict__ Rm) {
    extern __shared__ __align__(16) float Rs[];   // [RANK][KS] = 128 KB

    const int tid   = threadIdx.x;
    const int warp  = tid >> 5;
    const int lane  = tid & 31;
    const int ks    = blockIdx.x & (KSLICES - 1);
    const int tile  = blockIdx.x >> 1;
    const int k0    = ks * KS;
    const int tokq  = warp >> 1;
    const int rbase = (warp & 1) * 8;
    const int tok0  = tile * 32 + tokq * 4;

#pragma unroll
    for (int j = 0; j < 16; j++) {
        const int linear = tid + 512 * j;
        const int row    = linear >> 9;
        const int colf   = (linear & 511) << 2;
        *reinterpret_cast<float4*>(&Rs[row * KS + colf]) =
            *reinterpret_cast<const float4*>(&Rm[(size_t)row * IN_CH + k0 + colf]);
    }
    __syncthreads();

    u64 acc[4][8];
#pragma unroll
    for (int t = 0; t < 4; t++)
#pragma unroll
        for (int r = 0; r < 8; r++) acc[t][r] = 0ull;

    const float* xr = x + (size_t)tok0 * IN_CH + k0 + lane * 4;
    const float* Rw = Rs + (size_t)rbase * KS + lane * 4;

#pragma unroll 4
    for (int i = 0; i < KS / 128; i++) {
        const int kk = i * 128;
        const uint4 xv0 = *reinterpret_cast<const uint4*>(xr + 0 * IN_CH + kk);
        const uint4 xv1 = *reinterpret_cast<const uint4*>(xr + 1 * IN_CH + kk);
        const uint4 xv2 = *reinterpret_cast<const uint4*>(xr + 2 * IN_CH + kk);
        const uint4 xv3 = *reinterpret_cast<const uint4*>(xr + 3 * IN_CH + kk);
        const ulonglong2 x0 = *reinterpret_cast<const ulonglong2*>(&xv0);
        const ulonglong2 x1 = *reinterpret_cast<const ulonglong2*>(&xv1);
        const ulonglong2 x2 = *reinterpret_cast<const ulonglong2*>(&xv2);
        const ulonglong2 x3 = *reinterpret_cast<const ulonglong2*>(&xv3);
#pragma unroll
        for (int r = 0; r < 8; r++) {
            const ulonglong2 rv =
                *reinterpret_cast<const ulonglong2*>(Rw + (size_t)r * KS + kk);
            acc[0][r] = f2fma(x0.x, rv.x, acc[0][r]);
            acc[0][r] = f2fma(x0.y, rv.y, acc[0][r]);
            acc[1][r] = f2fma(x1.x, rv.x, acc[1][r]);
            acc[1][r] = f2fma(x1.y, rv.y, acc[1][r]);
            acc[2][r] = f2fma(x2.x, rv.x, acc[2][r]);
            acc[2][r] = f2fma(x2.y, rv.y, acc[2][r]);
            acc[3][r] = f2fma(x3.x, rv.x, acc[3][r]);
            acc[3][r] = f2fma(x3.y, rv.y, acc[3][r]);
        }
    }

#pragma unroll
    for (int t = 0; t < 4; t++) {
        float s[8];
#pragma unroll
        for (int r = 0; r < 8; r++) {
            float2 v = *reinterpret_cast<float2*>(&acc[t][r]);
            s[r] = v.x + v.y;
        }
#pragma unroll
        for (int off = 16; off > 0; off >>= 1) {
#pragma unroll
            for (int r = 0; r < 8; r++)
                s[r] += __shfl_xor_sync(0xffffffffu, s[r], off);
        }
        if (lane == 0) {
            float4* o = reinterpret_cast<float4*>(&g_tp[ks][tok0 + t][rbase]);
            o[0] = make_float4(s[0], s[1], s[2], s[3]);
            o[1] = make_float4(s[4], s[5], s[6], s[7]);
        }
    }
}

// ----------------------------------------------------------------------------
// Kernel 2 (round-1 geometry, 37 us) + PAIRED-RANK inner loop:
// ts2 read as broadcast LDS.128 covering (r, r+1) -> smem cycles per FFMA2
// cut 1.5x -> crossbar no longer the binding pipe.
// Tile: 32 tokens x 512 outputs, 128 thr.
// ----------------------------------------------------------------------------
__global__ void __launch_bounds__(128)
k2_tLt(const float* __restrict__ Lm, const float* __restrict__ bias,
       float* __restrict__ out) {
    __shared__ __align__(16) float Lt[16][512];     // Lt[r][o_local]
    __shared__ __align__(16) u64   ts2[32][16];     // splatted t[tok][r]

    const int tid = threadIdx.x;
    const int bt = blockIdx.x >> 3;     // token tile 0..255
    const int bo = blockIdx.x & 7;      // o chunk 0..7
    const int obase   = bo * 512;
    const int tokbase = bt * 32;

    // stage L chunk transposed: 512 rows of 16 floats
#pragma unroll
    for (int j = 0; j < 4; j++) {
        const int ol = tid + 128 * j;
        const float4* lr = reinterpret_cast<const float4*>(Lm + (size_t)(obase + ol) * RANK);
        float4 a = lr[0], b = lr[1], c = lr[2], d = lr[3];
        Lt[0][ol]  = a.x; Lt[1][ol]  = a.y; Lt[2][ol]  = a.z; Lt[3][ol]  = a.w;
        Lt[4][ol]  = b.x; Lt[5][ol]  = b.y; Lt[6][ol]  = b.z; Lt[7][ol]  = b.w;
        Lt[8][ol]  = c.x; Lt[9][ol]  = c.y; Lt[10][ol] = c.z; Lt[11][ol] = c.w;
        Lt[12][ol] = d.x; Lt[13][ol] = d.y; Lt[14][ol] = d.z; Lt[15][ol] = d.w;
    }

    // stage t rows: sum the 2 k-slice partials, then splat to f32x2
    {
        const float4 p0 = *(reinterpret_cast<const float4*>(&g_tp[0][tokbase][0]) + tid);
        const float4 p1 = *(reinterpret_cast<const float4*>(&g_tp[1][tokbase][0]) + tid);
        const int tok = tid >> 2;
        const int r0  = (tid & 3) * 4;
        ts2[tok][r0 + 0] = splat2(p0.x + p1.x);
        ts2[tok][r0 + 1] = splat2(p0.y + p1.y);
        ts2[tok][r0 + 2] = splat2(p0.z + p1.z);
        ts2[tok][r0 + 3] = splat2(p0.w + p1.w);
    }

    const ulonglong2 bv = *reinterpret_cast<const ulonglong2*>(bias + obase + tid * 4);
    __syncthreads();

    const int o4 = tid * 4;
#pragma unroll 1
    for (int tb = 0; tb < 4; tb++) {
        u64 accA[8], accB[8];
#pragma unroll
        for (int tk = 0; tk < 8; tk++) { accA[tk] = bv.x; accB[tk] = bv.y; }

#pragma unroll
        for (int r = 0; r < 16; r += 2) {
            const ulonglong2 Lv0 = *reinterpret_cast<const ulonglong2*>(&Lt[r][o4]);
            const ulonglong2 Lv1 = *reinterpret_cast<const ulonglong2*>(&Lt[r + 1][o4]);
#pragma unroll
            for (int tk = 0; tk < 8; tk++) {
                // one broadcast LDS.128: both splatted ranks (r, r+1)
                const ulonglong2 tp =
                    *reinterpret_cast<const ulonglong2*>(&ts2[tb * 8 + tk][r]);
                accA[tk] = f2fma(tp.x, Lv0.x, accA[tk]);
                accB[tk] = f2fma(tp.x, Lv0.y, accB[tk]);
                accA[tk] = f2fma(tp.y, Lv1.x, accA[tk]);
                accB[tk] = f2fma(tp.y, Lv1.y, accB[tk]);
            }
        }

#pragma unroll
        for (int tk = 0; tk < 8; tk++) {
            ulonglong2 o;
            o.x = accA[tk];
            o.y = accB[tk];
            *reinterpret_cast<ulonglong2*>(
                out + (size_t)(tokbase + tb * 8 + tk) * OUT_CH + obase + o4) = o;
        }
    }
}

extern "C" void kernel_launch(void* const* d_in, const int* in_sizes, int n_in,
                              void* d_out, int out_size) {
    (void)in_sizes; (void)n_in; (void)out_size;
    const float* x    = (const float*)d_in[0];   // [8192, 4096]
    const float* Lm   = (const float*)d_in[1];   // [4096, 16]
    const float* Rm   = (const float*)d_in[2];   // [16, 4096]
    const float* bias = (const float*)d_in[3];   // [4096]
    float* out = (float*)d_out;                  // [8192, 4096]

    static int attr_done = 0;
    if (!attr_done) {
        cudaFuncSetAttribute(k1_xRt, cudaFuncAttributeMaxDynamicSharedMemorySize, K1_SMEM);
        attr_done = 1;
    }

    k1_xRt<<<(N_TOKENS / 32) * KSLICES, 512, K1_SMEM>>>(x, Rm);
    k2_tLt<<<(N_TOKENS / 32) * (OUT_CH / 512), 128>>>(Lm, bias, out);
}